// round 1
// baseline (speedup 1.0000x reference)
#include <cuda_runtime.h>

#define Bb 8
#define Ss 512
#define Ee 64
#define Hh 8
#define NTOKH (Bb*Ss*Hh)   // 32768
#define ROWS_PER_BLK 128

// scratch (no cudaMalloc allowed)
__device__ float g_q[Bb*Hh*Ss*8];     // q in [B,H,S,8] layout
__device__ float g_ctx[Bb*Ss*Ee];     // attention context, [B,S,E]

// ---------------------------------------------------------------------------
// Kernel 1: analytic quantum heads.
// z_w = prod_{j<=w} cos(a_j) for w>=1 ; z_0 = prod_{j=1..7} cos(a_j)
// ---------------------------------------------------------------------------
__global__ void qheads_kernel(const float* __restrict__ x,
                              const float* __restrict__ theta) {
    int n = blockIdx.x * blockDim.x + threadIdx.x;
    if (n >= NTOKH) return;

    const float4* x4 = reinterpret_cast<const float4*>(x);
    float4 x0 = x4[n * 2];
    float4 x1 = x4[n * 2 + 1];
    float a[8] = {x0.x, x0.y, x0.z, x0.w, x1.x, x1.y, x1.z, x1.w};

    float c[8];
#pragma unroll
    for (int w = 0; w < 8; w++) c[w] = cosf(a[w] + theta[w]);

    float z[8];
    float pre = c[0];
#pragma unroll
    for (int w = 1; w < 8; w++) { pre *= c[w]; z[w] = pre; }
    float suf = 1.0f;
#pragma unroll
    for (int w = 7; w >= 1; w--) suf *= c[w];
    z[0] = suf;

    // n = (b*S + s)*H + h  ->  write at [b,h,s,:]
    int h  = n & (Hh - 1);
    int bs = n >> 3;           // b*S + s
    int s  = bs & (Ss - 1);
    int b  = bs >> 9;
    float4* o4 = reinterpret_cast<float4*>(g_q + (((b * Hh + h) * Ss) + s) * 8);
    o4[0] = make_float4(z[0], z[1], z[2], z[3]);
    o4[1] = make_float4(z[4], z[5], z[6], z[7]);
}

// ---------------------------------------------------------------------------
// Kernel 2: per-(b,h) self-attention, q=k=v, S=512, d=8.
// Scores bounded in [-sqrt(8), sqrt(8)] -> softmax without max subtraction.
// grid = (B*H, S/ROWS_PER_BLK), block = ROWS_PER_BLK
// ---------------------------------------------------------------------------
__global__ void attn_kernel() {
    __shared__ float qs[Ss * 8];   // 16 KB: full q tile for this (b,h)
    const int bh  = blockIdx.x;
    const int tid = threadIdx.x;

    const float4* qb4 = reinterpret_cast<const float4*>(g_q + bh * Ss * 8);
    float4* qs4 = reinterpret_cast<float4*>(qs);
#pragma unroll
    for (int i = tid; i < Ss * 2; i += ROWS_PER_BLK) qs4[i] = qb4[i];
    __syncthreads();

    const int s = blockIdx.y * ROWS_PER_BLK + tid;
    const float scale = 0.35355339059327373f;   // 1/sqrt(8)
    float myq[8];
#pragma unroll
    for (int d = 0; d < 8; d++) myq[d] = qs[s * 8 + d] * scale;

    float l = 0.0f;
    float acc[8];
#pragma unroll
    for (int d = 0; d < 8; d++) acc[d] = 0.0f;

    for (int t = 0; t < Ss; t++) {
        float4 r0 = qs4[t * 2];        // broadcast LDS.128
        float4 r1 = qs4[t * 2 + 1];
        float sc = myq[0] * r0.x;
        sc = fmaf(myq[1], r0.y, sc);
        sc = fmaf(myq[2], r0.z, sc);
        sc = fmaf(myq[3], r0.w, sc);
        sc = fmaf(myq[4], r1.x, sc);
        sc = fmaf(myq[5], r1.y, sc);
        sc = fmaf(myq[6], r1.z, sc);
        sc = fmaf(myq[7], r1.w, sc);
        float p = __expf(sc);
        l += p;
        acc[0] = fmaf(p, r0.x, acc[0]);
        acc[1] = fmaf(p, r0.y, acc[1]);
        acc[2] = fmaf(p, r0.z, acc[2]);
        acc[3] = fmaf(p, r0.w, acc[3]);
        acc[4] = fmaf(p, r1.x, acc[4]);
        acc[5] = fmaf(p, r1.y, acc[5]);
        acc[6] = fmaf(p, r1.z, acc[6]);
        acc[7] = fmaf(p, r1.w, acc[7]);
    }

    float inv = __frcp_rn(l);
    int b = bh >> 3, h = bh & 7;
    float4* o4 = reinterpret_cast<float4*>(g_ctx + ((b * Ss + s) * Ee + h * 8));
    o4[0] = make_float4(acc[0] * inv, acc[1] * inv, acc[2] * inv, acc[3] * inv);
    o4[1] = make_float4(acc[4] * inv, acc[5] * inv, acc[6] * inv, acc[7] * inv);
}

// ---------------------------------------------------------------------------
// Kernel 3: out = ctx @ W_o^T + b_o.  ctx: [4096, 64], W_o: [64, 64].
// block = 256 threads, 4 rows x 64 cols per block; W transposed + padded smem.
// ---------------------------------------------------------------------------
__global__ void proj_kernel(const float* __restrict__ Wo,
                            const float* __restrict__ bo,
                            float* __restrict__ out) {
    __shared__ float Wt[64 * 65];     // Wt[e*65 + j] = Wo[j*64 + e]
    __shared__ float rows[4 * 64];
    const int tid = threadIdx.x;

    for (int idx = tid; idx < 4096; idx += 256) {
        int j = idx >> 6, e = idx & 63;
        Wt[e * 65 + j] = Wo[idx];
    }
    const int row0 = blockIdx.x * 4;
    rows[tid] = g_ctx[row0 * 64 + tid];
    __syncthreads();

    const int r = tid >> 6, j = tid & 63;
    float acc = bo[j];
    const float* cr = rows + r * 64;
#pragma unroll
    for (int e = 0; e < 64; e++) acc = fmaf(cr[e], Wt[e * 65 + j], acc);
    out[(row0 + r) * 64 + j] = acc;
}

// ---------------------------------------------------------------------------
extern "C" void kernel_launch(void* const* d_in, const int* in_sizes, int n_in,
                              void* d_out, int out_size) {
    const float* x     = (const float*)d_in[0];
    const float* theta = (const float*)d_in[1];
    const float* Wo    = (const float*)d_in[2];
    const float* bo    = (const float*)d_in[3];
    float* out = (float*)d_out;
    (void)in_sizes; (void)n_in; (void)out_size;

    qheads_kernel<<<NTOKH / 256, 256>>>(x, theta);
    attn_kernel<<<dim3(Bb * Hh, Ss / ROWS_PER_BLK), ROWS_PER_BLK>>>();
    proj_kernel<<<(Bb * Ss) / 4, 256>>>(Wo, bo, out);
}

// round 2
// speedup vs baseline: 1.1102x; 1.1102x over previous
#include <cuda_runtime.h>
#include <cstdint>

#define Bb 8
#define Ss 512
#define Ee 64
#define Hh 8
#define NTOKH (Bb*Ss*Hh)   // 32768
#define ROWS_PER_BLK 128
#define PROJ_ROWS 16

// scratch (no cudaMalloc allowed)
__device__ float g_q[Bb*Hh*Ss*8];     // q in [B,H,S,8] layout
__device__ float g_ctx[Bb*Ss*Ee];     // attention context, [B,S,E]

// packed fp32x2 helpers (sm_103a FFMA2 path)
#define FMA_X2(d, a, b, c) \
    asm("fma.rn.f32x2 %0, %1, %2, %3;" : "=l"(d) : "l"(a), "l"(b), "l"(c))
#define MUL_X2(d, a, b) \
    asm("mul.rn.f32x2 %0, %1, %2;" : "=l"(d) : "l"(a), "l"(b))

__device__ __forceinline__ uint64_t pack2(float lo, float hi) {
    uint64_t u;
    unsigned a = __float_as_uint(lo), b = __float_as_uint(hi);
    asm("mov.b64 %0, {%1, %2};" : "=l"(u) : "r"(a), "r"(b));
    return u;
}
__device__ __forceinline__ void unpack2(uint64_t u, float& lo, float& hi) {
    unsigned a, b;
    asm("mov.b64 {%0, %1}, %2;" : "=r"(a), "=r"(b) : "l"(u));
    lo = __uint_as_float(a); hi = __uint_as_float(b);
}

// ---------------------------------------------------------------------------
// Kernel 1: analytic quantum heads.
// z_w = prod_{j<=w} cos(a_j) for w>=1 ; z_0 = prod_{j=1..7} cos(a_j)
// ---------------------------------------------------------------------------
__global__ void qheads_kernel(const float* __restrict__ x,
                              const float* __restrict__ theta) {
    int n = blockIdx.x * blockDim.x + threadIdx.x;
    if (n >= NTOKH) return;

    const float4* x4 = reinterpret_cast<const float4*>(x);
    float4 x0 = x4[n * 2];
    float4 x1 = x4[n * 2 + 1];
    float a[8] = {x0.x, x0.y, x0.z, x0.w, x1.x, x1.y, x1.z, x1.w};

    float c[8];
#pragma unroll
    for (int w = 0; w < 8; w++) c[w] = __cosf(a[w] + theta[w]);

    float z[8];
    float pre = c[0];
#pragma unroll
    for (int w = 1; w < 8; w++) { pre *= c[w]; z[w] = pre; }
    float suf = 1.0f;
#pragma unroll
    for (int w = 7; w >= 1; w--) suf *= c[w];
    z[0] = suf;

    // n = (b*S + s)*H + h  ->  write at [b,h,s,:]
    int h  = n & (Hh - 1);
    int bs = n >> 3;           // b*S + s
    int s  = bs & (Ss - 1);
    int b  = bs >> 9;
    float4* o4 = reinterpret_cast<float4*>(g_q + (((b * Hh + h) * Ss) + s) * 8);
    o4[0] = make_float4(z[0], z[1], z[2], z[3]);
    o4[1] = make_float4(z[4], z[5], z[6], z[7]);
}

// ---------------------------------------------------------------------------
// Kernel 2: per-(b,h) self-attention, q=k=v, S=512, d=8.
// Packed f32x2 FMAs; log2e/sqrt(8) folded into query -> raw ex2.approx.
// Scores bounded |sc| <= sqrt(8)*log2e ~= 4.08 -> no max subtraction needed.
// grid = (B*H, S/ROWS_PER_BLK), block = ROWS_PER_BLK
// ---------------------------------------------------------------------------
__global__ void attn_kernel() {
    __shared__ float qs[Ss * 8];   // 16 KB: full q tile for this (b,h)
    const int bh  = blockIdx.x;
    const int tid = threadIdx.x;

    const float4* qb4 = reinterpret_cast<const float4*>(g_q + bh * Ss * 8);
    float4* qs4 = reinterpret_cast<float4*>(qs);
#pragma unroll
    for (int i = tid; i < Ss * 2; i += ROWS_PER_BLK) qs4[i] = qb4[i];
    __syncthreads();

    const int s = blockIdx.y * ROWS_PER_BLK + tid;
    // 1/sqrt(8) * log2(e) folded into the query registers
    const float kscale = 0.35355339059327373f * 1.4426950408889634f;
    float m[8];
#pragma unroll
    for (int d = 0; d < 8; d++) m[d] = qs[s * 8 + d] * kscale;
    uint64_t q01 = pack2(m[0], m[1]);
    uint64_t q23 = pack2(m[2], m[3]);
    uint64_t q45 = pack2(m[4], m[5]);
    uint64_t q67 = pack2(m[6], m[7]);

    uint64_t a0 = 0, a1 = 0, a2 = 0, a3 = 0;   // packed +0.0f pairs
    float l = 0.0f;

    const ulonglong2* k8 = reinterpret_cast<const ulonglong2*>(qs);
#pragma unroll 8
    for (int t = 0; t < Ss; t++) {
        ulonglong2 ka = k8[2 * t];       // key row, packed pairs (LDS.128)
        ulonglong2 kb = k8[2 * t + 1];
        uint64_t sp;
        MUL_X2(sp, q01, ka.x);
        FMA_X2(sp, q23, ka.y, sp);
        FMA_X2(sp, q45, kb.x, sp);
        FMA_X2(sp, q67, kb.y, sp);
        float slo, shi;
        unpack2(sp, slo, shi);
        float sc = slo + shi;
        float p;
        asm("ex2.approx.f32 %0, %1;" : "=f"(p) : "f"(sc));
        l += p;
        uint64_t pp = pack2(p, p);
        FMA_X2(a0, pp, ka.x, a0);
        FMA_X2(a1, pp, ka.y, a1);
        FMA_X2(a2, pp, kb.x, a2);
        FMA_X2(a3, pp, kb.y, a3);
    }

    float inv = __frcp_rn(l);
    float r[8];
    unpack2(a0, r[0], r[1]);
    unpack2(a1, r[2], r[3]);
    unpack2(a2, r[4], r[5]);
    unpack2(a3, r[6], r[7]);

    int b = bh >> 3, h = bh & 7;
    float4* o4 = reinterpret_cast<float4*>(g_ctx + ((b * Ss + s) * Ee + h * 8));
    o4[0] = make_float4(r[0] * inv, r[1] * inv, r[2] * inv, r[3] * inv);
    o4[1] = make_float4(r[4] * inv, r[5] * inv, r[6] * inv, r[7] * inv);
}

// ---------------------------------------------------------------------------
// Kernel 3: out = ctx @ W_o^T + b_o.  ctx: [4096, 64], W_o: [64, 64].
// 16 rows/block (amortize the 16.6KB W-transpose fill), 4 outputs/thread.
// ---------------------------------------------------------------------------
__global__ void proj_kernel(const float* __restrict__ Wo,
                            const float* __restrict__ bo,
                            float* __restrict__ out) {
    __shared__ float Wt[64 * 65];          // Wt[e*65 + j] = Wo[j*64 + e]
    __shared__ float rows[PROJ_ROWS * 64];
    const int tid = threadIdx.x;           // 256

    for (int idx = tid; idx < 4096; idx += 256) {
        int j = idx >> 6, e = idx & 63;
        Wt[e * 65 + j] = Wo[idx];
    }
    const int row0 = blockIdx.x * PROJ_ROWS;
    reinterpret_cast<float4*>(rows)[tid] =
        reinterpret_cast<const float4*>(g_ctx + row0 * 64)[tid];
    __syncthreads();

    const int j = tid & 63, rb = tid >> 6;     // rb in 0..3
    float bj = bo[j];
    float acc0 = bj, acc1 = bj, acc2 = bj, acc3 = bj;
#pragma unroll
    for (int e = 0; e < 64; e++) {
        float w = Wt[e * 65 + j];
        acc0 = fmaf(rows[(rb +  0) * 64 + e], w, acc0);
        acc1 = fmaf(rows[(rb +  4) * 64 + e], w, acc1);
        acc2 = fmaf(rows[(rb +  8) * 64 + e], w, acc2);
        acc3 = fmaf(rows[(rb + 12) * 64 + e], w, acc3);
    }
    out[(row0 + rb +  0) * 64 + j] = acc0;
    out[(row0 + rb +  4) * 64 + j] = acc1;
    out[(row0 + rb +  8) * 64 + j] = acc2;
    out[(row0 + rb + 12) * 64 + j] = acc3;
}

// ---------------------------------------------------------------------------
extern "C" void kernel_launch(void* const* d_in, const int* in_sizes, int n_in,
                              void* d_out, int out_size) {
    const float* x     = (const float*)d_in[0];
    const float* theta = (const float*)d_in[1];
    const float* Wo    = (const float*)d_in[2];
    const float* bo    = (const float*)d_in[3];
    float* out = (float*)d_out;
    (void)in_sizes; (void)n_in; (void)out_size;

    qheads_kernel<<<NTOKH / 256, 256>>>(x, theta);
    attn_kernel<<<dim3(Bb * Hh, Ss / ROWS_PER_BLK), ROWS_PER_BLK>>>();
    proj_kernel<<<(Bb * Ss) / PROJ_ROWS, 256>>>(Wo, bo, out);
}

// round 5
// speedup vs baseline: 1.2977x; 1.1689x over previous
#include <cuda_runtime.h>
#include <cstdint>

#define Bb 8
#define Ss 512
#define Ee 64
#define Hh 8
#define PROJ_ROWS 16

// scratch (no cudaMalloc allowed)
__device__ float g_ctx[Bb*Ss*Ee];     // attention context, [B,S,E]

// packed fp32x2 helpers (sm_103a FFMA2 path)
#define FMA_X2(d, a, b, c) \
    asm("fma.rn.f32x2 %0, %1, %2, %3;" : "=l"(d) : "l"(a), "l"(b), "l"(c))
#define MUL_X2(d, a, b) \
    asm("mul.rn.f32x2 %0, %1, %2;" : "=l"(d) : "l"(a), "l"(b))

__device__ __forceinline__ uint64_t pack2(float lo, float hi) {
    uint64_t u;
    unsigned a = __float_as_uint(lo), b = __float_as_uint(hi);
    asm("mov.b64 %0, {%1, %2};" : "=l"(u) : "r"(a), "r"(b));
    return u;
}
__device__ __forceinline__ void unpack2(uint64_t u, float& lo, float& hi) {
    unsigned a, b;
    asm("mov.b64 {%0, %1}, %2;" : "=r"(a), "=r"(b) : "l"(u));
    lo = __uint_as_float(a); hi = __uint_as_float(b);
}

// ---------------------------------------------------------------------------
// Fused kernel: quantum heads (analytic) + per-(b,h) self-attention.
//   z_w = prod_{j<=w} cos(x_j+theta_j) for w>=1 ; z_0 = prod_{j=1..7} cos(..)
//   then softmax(q q^T / sqrt(8)) q  with q=k=v, S=512, d=8.
// grid = B*H*2 = 128 blocks (single wave on 148 SMs), block = 256 threads.
// Block (bh, half): builds the full 512x8 q-tile for bh in smem, then
// processes rows [half*256, half*256+256).
// ---------------------------------------------------------------------------
__global__ __launch_bounds__(256) void attn_fused_kernel(
        const float* __restrict__ x,
        const float* __restrict__ theta) {
    __shared__ float qs[Ss * 8];   // 16 KB: full q tile for this (b,h)
    const int tid  = threadIdx.x;
    const int bh   = blockIdx.x >> 1;
    const int half = blockIdx.x & 1;
    const int b = bh >> 3, h = bh & 7;

    // ---- build q tile: each thread computes rows tid and tid+256 ----
    float th[8];
#pragma unroll
    for (int w = 0; w < 8; w++) th[w] = __ldg(theta + w);

#pragma unroll
    for (int rr = 0; rr < 2; rr++) {
        int s = tid + rr * 256;
        const float4* xr = reinterpret_cast<const float4*>(
            x + ((b * Ss + s) * Ee + h * 8));
        float4 x0 = xr[0];
        float4 x1 = xr[1];
        float a[8] = {x0.x, x0.y, x0.z, x0.w, x1.x, x1.y, x1.z, x1.w};
        float c[8];
#pragma unroll
        for (int w = 0; w < 8; w++) c[w] = __cosf(a[w] + th[w]);
        float z[8];
        float pre = c[0];
#pragma unroll
        for (int w = 1; w < 8; w++) { pre *= c[w]; z[w] = pre; }
        float suf = 1.0f;
#pragma unroll
        for (int w = 7; w >= 1; w--) suf *= c[w];
        z[0] = suf;
        float4* o4 = reinterpret_cast<float4*>(qs + s * 8);
        o4[0] = make_float4(z[0], z[1], z[2], z[3]);
        o4[1] = make_float4(z[4], z[5], z[6], z[7]);
    }
    __syncthreads();

    // ---- attention for row s ----
    const int s = half * 256 + tid;
    // 1/sqrt(8) * log2(e) folded into the query registers -> raw ex2
    const float kscale = 0.35355339059327373f * 1.4426950408889634f;
    float m[8];
#pragma unroll
    for (int d = 0; d < 8; d++) m[d] = qs[s * 8 + d] * kscale;
    uint64_t q01 = pack2(m[0], m[1]);
    uint64_t q23 = pack2(m[2], m[3]);
    uint64_t q45 = pack2(m[4], m[5]);
    uint64_t q67 = pack2(m[6], m[7]);

    uint64_t a0 = 0, a1 = 0, a2 = 0, a3 = 0;   // packed +0.0f pairs
    float l = 0.0f;

    const ulonglong2* k8 = reinterpret_cast<const ulonglong2*>(qs);
#pragma unroll 8
    for (int t = 0; t < Ss; t++) {
        ulonglong2 ka = k8[2 * t];       // key row, packed pairs (broadcast LDS.128)
        ulonglong2 kb = k8[2 * t + 1];
        uint64_t sp;
        MUL_X2(sp, q01, ka.x);
        FMA_X2(sp, q23, ka.y, sp);
        FMA_X2(sp, q45, kb.x, sp);
        FMA_X2(sp, q67, kb.y, sp);
        float slo, shi;
        unpack2(sp, slo, shi);
        float sc = slo + shi;
        float p;
        asm("ex2.approx.f32 %0, %1;" : "=f"(p) : "f"(sc));
        l += p;
        uint64_t pp = pack2(p, p);
        FMA_X2(a0, pp, ka.x, a0);
        FMA_X2(a1, pp, ka.y, a1);
        FMA_X2(a2, pp, kb.x, a2);
        FMA_X2(a3, pp, kb.y, a3);
    }

    float inv = __frcp_rn(l);
    float r[8];
    unpack2(a0, r[0], r[1]);
    unpack2(a1, r[2], r[3]);
    unpack2(a2, r[4], r[5]);
    unpack2(a3, r[6], r[7]);

    float4* o4 = reinterpret_cast<float4*>(g_ctx + ((b * Ss + s) * Ee + h * 8));
    o4[0] = make_float4(r[0] * inv, r[1] * inv, r[2] * inv, r[3] * inv);
    o4[1] = make_float4(r[4] * inv, r[5] * inv, r[6] * inv, r[7] * inv);
}

// ---------------------------------------------------------------------------
// Kernel 2: out = ctx @ W_o^T + b_o.  ctx: [4096, 64], W_o: [64, 64].
// 16 rows/block (amortize the 16.6KB W-transpose fill), 4 outputs/thread.
// ---------------------------------------------------------------------------
__global__ void proj_kernel(const float* __restrict__ Wo,
                            const float* __restrict__ bo,
                            float* __restrict__ out) {
    __shared__ float Wt[64 * 65];          // Wt[e*65 + j] = Wo[j*64 + e]
    __shared__ float rows[PROJ_ROWS * 64];
    const int tid = threadIdx.x;           // 256

    for (int idx = tid; idx < 4096; idx += 256) {
        int j = idx >> 6, e = idx & 63;
        Wt[e * 65 + j] = Wo[idx];
    }
    const int row0 = blockIdx.x * PROJ_ROWS;
    reinterpret_cast<float4*>(rows)[tid] =
        reinterpret_cast<const float4*>(g_ctx + row0 * 64)[tid];
    __syncthreads();

    const int j = tid & 63, rb = tid >> 6;     // rb in 0..3
    float bj = bo[j];
    float acc0 = bj, acc1 = bj, acc2 = bj, acc3 = bj;
#pragma unroll
    for (int e = 0; e < 64; e++) {
        float w = Wt[e * 65 + j];
        acc0 = fmaf(rows[(rb +  0) * 64 + e], w, acc0);
        acc1 = fmaf(rows[(rb +  4) * 64 + e], w, acc1);
        acc2 = fmaf(rows[(rb +  8) * 64 + e], w, acc2);
        acc3 = fmaf(rows[(rb + 12) * 64 + e], w, acc3);
    }
    out[(row0 + rb +  0) * 64 + j] = acc0;
    out[(row0 + rb +  4) * 64 + j] = acc1;
    out[(row0 + rb +  8) * 64 + j] = acc2;
    out[(row0 + rb + 12) * 64 + j] = acc3;
}

// ---------------------------------------------------------------------------
extern "C" void kernel_launch(void* const* d_in, const int* in_sizes, int n_in,
                              void* d_out, int out_size) {
    const float* x     = (const float*)d_in[0];
    const float* theta = (const float*)d_in[1];
    const float* Wo    = (const float*)d_in[2];
    const float* bo    = (const float*)d_in[3];
    float* out = (float*)d_out;
    (void)in_sizes; (void)n_in; (void)out_size;

    attn_fused_kernel<<<Bb * Hh * 2, 256>>>(x, theta);
    proj_kernel<<<(Bb * Ss) / PROJ_ROWS, 256>>>(Wo, bo, out);
}

// round 8
// speedup vs baseline: 1.7347x; 1.3367x over previous
#include <cuda_runtime.h>
#include <cstdint>

#define Bb 8
#define Ss 512
#define Ee 64
#define Hh 8
#define PROJ_ROWS 32

// scratch (no cudaMalloc allowed)
__device__ float g_ctx[Bb*Ss*Ee];     // attention context, [B,S,E]

// packed fp32x2 helpers (sm_103a FFMA2 path)
#define FMA_X2(d, a, b, c) \
    asm("fma.rn.f32x2 %0, %1, %2, %3;" : "=l"(d) : "l"(a), "l"(b), "l"(c))
#define MUL_X2(d, a, b) \
    asm("mul.rn.f32x2 %0, %1, %2;" : "=l"(d) : "l"(a), "l"(b))
#define ADD_X2(d, a, b) \
    asm("add.rn.f32x2 %0, %1, %2;" : "=l"(d) : "l"(a), "l"(b))

__device__ __forceinline__ uint64_t pack2(float lo, float hi) {
    uint64_t u;
    unsigned a = __float_as_uint(lo), b = __float_as_uint(hi);
    asm("mov.b64 %0, {%1, %2};" : "=l"(u) : "r"(a), "r"(b));
    return u;
}
__device__ __forceinline__ void unpack2(uint64_t u, float& lo, float& hi) {
    unsigned a, b;
    asm("mov.b64 {%0, %1}, %2;" : "=r"(a), "=r"(b) : "l"(u));
    lo = __uint_as_float(a); hi = __uint_as_float(b);
}

// ---------------------------------------------------------------------------
// Fused kernel: analytic quantum heads + self-attention, packed over KEYS.
//   q-tile stored TRANSPOSED in smem: qsT[d*512 + s].
//   Scores for key pairs (t,t+1) computed in packed f32x2 lanes -> no
//   horizontal add; accumulators are packed per-d over key parity, reduced
//   once at the end.
// grid = B*H*2 = 128 blocks (single wave), block = 512 threads:
//   r = tid & 255 : query row within this block's half
//   g = tid >> 8  : key group (keys [g*256, g*256+256))
// ---------------------------------------------------------------------------
__global__ __launch_bounds__(512) void attn_fused_kernel(
        const float* __restrict__ x,
        const float* __restrict__ theta) {
    __shared__ float qsT[8 * Ss];             // 16 KB, transposed q tile
    __shared__ uint64_t part[256 * 9];        // 18 KB, group-1 partials
    const int tid  = threadIdx.x;
    const int bh   = blockIdx.x >> 1;
    const int half = blockIdx.x & 1;
    const int b = bh >> 3, h = bh & 7;

    // ---- build transposed q tile: each thread computes row tid ----
    {
        float th[8];
#pragma unroll
        for (int w = 0; w < 8; w++) th[w] = __ldg(theta + w);
        const float4* xr = reinterpret_cast<const float4*>(
            x + ((b * Ss + tid) * Ee + h * 8));
        float4 x0 = xr[0];
        float4 x1 = xr[1];
        float a[8] = {x0.x, x0.y, x0.z, x0.w, x1.x, x1.y, x1.z, x1.w};
        float c[8];
#pragma unroll
        for (int w = 0; w < 8; w++) c[w] = __cosf(a[w] + th[w]);
        float z[8];
        float pre = c[0];
#pragma unroll
        for (int w = 1; w < 8; w++) { pre *= c[w]; z[w] = pre; }
        float suf = 1.0f;
#pragma unroll
        for (int w = 7; w >= 1; w--) suf *= c[w];
        z[0] = suf;
#pragma unroll
        for (int d = 0; d < 8; d++) qsT[d * Ss + tid] = z[d];
    }
    __syncthreads();

    const int r = tid & 255;
    const int g = tid >> 8;
    const int s = half * 256 + r;

    // query, scaled by 1/sqrt(8)*log2(e), broadcast into both packed lanes
    const float kscale = 0.35355339059327373f * 1.4426950408889634f;
    uint64_t mP[8];
#pragma unroll
    for (int d = 0; d < 8; d++) {
        float m = qsT[d * Ss + s] * kscale;
        mP[d] = pack2(m, m);
    }

    uint64_t acc[8];                     // packed per-d, over key parity
#pragma unroll
    for (int d = 0; d < 8; d++) acc[d] = 0;
    uint64_t lP = 0;

    const int t0 = g * 256;
#pragma unroll 1
    for (int t = t0; t < t0 + 256; t += 4) {
        // keys t..t+3 for all 8 dims: broadcast LDS.128, 2 packed pairs each
        ulonglong2 kd[8];
#pragma unroll
        for (int d = 0; d < 8; d++)
            kd[d] = *reinterpret_cast<const ulonglong2*>(qsT + d * Ss + t);

        uint64_t sAB, sCD;               // scores (t,t+1) and (t+2,t+3)
        MUL_X2(sAB, mP[0], kd[0].x);
        MUL_X2(sCD, mP[0], kd[0].y);
#pragma unroll
        for (int d = 1; d < 8; d++) {
            FMA_X2(sAB, mP[d], kd[d].x, sAB);
            FMA_X2(sCD, mP[d], kd[d].y, sCD);
        }
        float s0, s1, s2, s3;
        unpack2(sAB, s0, s1);
        unpack2(sCD, s2, s3);
        float p0, p1, p2, p3;
        asm("ex2.approx.f32 %0, %1;" : "=f"(p0) : "f"(s0));
        asm("ex2.approx.f32 %0, %1;" : "=f"(p1) : "f"(s1));
        asm("ex2.approx.f32 %0, %1;" : "=f"(p2) : "f"(s2));
        asm("ex2.approx.f32 %0, %1;" : "=f"(p3) : "f"(s3));
        uint64_t pAB = pack2(p0, p1);
        uint64_t pCD = pack2(p2, p3);
        ADD_X2(lP, lP, pAB);
        ADD_X2(lP, lP, pCD);
#pragma unroll
        for (int d = 0; d < 8; d++) {
            FMA_X2(acc[d], pAB, kd[d].x, acc[d]);
            FMA_X2(acc[d], pCD, kd[d].y, acc[d]);
        }
    }

    // ---- combine the two key groups ----
    if (g == 1) {
        uint64_t* pr = part + r * 9;
#pragma unroll
        for (int d = 0; d < 8; d++) pr[d] = acc[d];
        pr[8] = lP;
    }
    __syncthreads();
    if (g == 0) {
        const uint64_t* pr = part + r * 9;
#pragma unroll
        for (int d = 0; d < 8; d++) ADD_X2(acc[d], acc[d], pr[d]);
        ADD_X2(lP, lP, pr[8]);

        float lo, hi;
        unpack2(lP, lo, hi);
        float inv = __frcp_rn(lo + hi);
        float rr[8];
#pragma unroll
        for (int d = 0; d < 8; d++) {
            unpack2(acc[d], lo, hi);
            rr[d] = (lo + hi) * inv;
        }
        float4* o4 = reinterpret_cast<float4*>(
            g_ctx + ((b * Ss + s) * Ee + h * 8));
        o4[0] = make_float4(rr[0], rr[1], rr[2], rr[3]);
        o4[1] = make_float4(rr[4], rr[5], rr[6], rr[7]);
    }
}

// ---------------------------------------------------------------------------
// Kernel 2: out = ctx @ W_o^T + b_o.  ctx: [4096, 64], W_o: [64, 64].
// 32 rows/block (grid 128, single wave), 8 outputs/thread.
// ---------------------------------------------------------------------------
__global__ __launch_bounds__(256) void proj_kernel(
        const float* __restrict__ Wo,
        const float* __restrict__ bo,
        float* __restrict__ out) {
    __shared__ float Wt[64 * 65];             // Wt[e*65 + j] = Wo[j*64 + e]
    __shared__ float rows[PROJ_ROWS * 64];
    const int tid = threadIdx.x;              // 256

    // W fill: float4 loads, transposed scatter stores
    const float4* Wo4 = reinterpret_cast<const float4*>(Wo);
#pragma unroll
    for (int i = tid; i < 1024; i += 256) {
        float4 w = Wo4[i];
        int j = i >> 4, e0 = (i & 15) * 4;
        Wt[(e0 + 0) * 65 + j] = w.x;
        Wt[(e0 + 1) * 65 + j] = w.y;
        Wt[(e0 + 2) * 65 + j] = w.z;
        Wt[(e0 + 3) * 65 + j] = w.w;
    }
    const int row0 = blockIdx.x * PROJ_ROWS;
    const float4* c4 = reinterpret_cast<const float4*>(g_ctx + row0 * 64);
    float4* r4 = reinterpret_cast<float4*>(rows);
#pragma unroll
    for (int i = tid; i < PROJ_ROWS * 16; i += 256) r4[i] = c4[i];
    __syncthreads();

    const int j = tid & 63, rb = tid >> 6;    // rb in 0..3
    float bj = bo[j];
    float acc[8];
#pragma unroll
    for (int k = 0; k < 8; k++) acc[k] = bj;
#pragma unroll
    for (int e = 0; e < 64; e++) {
        float w = Wt[e * 65 + j];
#pragma unroll
        for (int k = 0; k < 8; k++)
            acc[k] = fmaf(rows[(rb + 4 * k) * 64 + e], w, acc[k]);
    }
#pragma unroll
    for (int k = 0; k < 8; k++)
        out[(row0 + rb + 4 * k) * 64 + j] = acc[k];
}

// ---------------------------------------------------------------------------
extern "C" void kernel_launch(void* const* d_in, const int* in_sizes, int n_in,
                              void* d_out, int out_size) {
    const float* x     = (const float*)d_in[0];
    const float* theta = (const float*)d_in[1];
    const float* Wo    = (const float*)d_in[2];
    const float* bo    = (const float*)d_in[3];
    float* out = (float*)d_out;
    (void)in_sizes; (void)n_in; (void)out_size;

    attn_fused_kernel<<<Bb * Hh * 2, 512>>>(x, theta);
    proj_kernel<<<(Bb * Ss) / PROJ_ROWS, 256>>>(Wo, bo, out);
}

// round 11
// speedup vs baseline: 1.7369x; 1.0013x over previous
#include <cuda_runtime.h>
#include <cstdint>

#define Bb 8
#define Ss 512
#define Ee 64
#define Hh 8
#define PROJ_ROWS 32

// scratch (no cudaMalloc allowed)
__device__ float g_ctx[Bb*Ss*Ee];     // attention context, [B,S,E]

// packed fp32x2 helpers (sm_103a FFMA2 path)
#define FMA_X2(d, a, b, c) \
    asm("fma.rn.f32x2 %0, %1, %2, %3;" : "=l"(d) : "l"(a), "l"(b), "l"(c))
#define MUL_X2(d, a, b) \
    asm("mul.rn.f32x2 %0, %1, %2;" : "=l"(d) : "l"(a), "l"(b))
#define ADD_X2(d, a, b) \
    asm("add.rn.f32x2 %0, %1, %2;" : "=l"(d) : "l"(a), "l"(b))

__device__ __forceinline__ uint64_t pack2(float lo, float hi) {
    uint64_t u;
    unsigned a = __float_as_uint(lo), b = __float_as_uint(hi);
    asm("mov.b64 %0, {%1, %2};" : "=l"(u) : "r"(a), "r"(b));
    return u;
}
__device__ __forceinline__ void unpack2(uint64_t u, float& lo, float& hi) {
    unsigned a, b;
    asm("mov.b64 {%0, %1}, %2;" : "=r"(a), "=r"(b) : "l"(u));
    lo = __uint_as_float(a); hi = __uint_as_float(b);
}

// ---------------------------------------------------------------------------
// Fused kernel: analytic quantum heads + self-attention.
//   2 query rows per thread, 4-way key split.
// grid = B*H*2 = 128 blocks (single wave), block = 512 threads:
//   pr = tid & 127 : query row pair (rows half*256+pr and +128)
//   g  = tid >> 7  : key group (keys [g*128, g*128+128))
// Keys loaded once per 4 keys serve both rows (LDS/key-row halved); 4
// independent packed score chains + 16 acc chains per iteration hide the
// FMA/ex2 latency. Partials combined via 3 sequential smem rounds.
// ---------------------------------------------------------------------------
__global__ __launch_bounds__(512) void attn_fused_kernel(
        const float* __restrict__ x,
        const float* __restrict__ theta) {
    __shared__ float qsT[8 * Ss];             // 16 KB, transposed q tile
    __shared__ uint64_t part[128 * 18];       // 18 KB, partial buffer
    const int tid  = threadIdx.x;
    const int bh   = blockIdx.x >> 1;
    const int half = blockIdx.x & 1;
    const int b = bh >> 3, h = bh & 7;

    // ---- build transposed q tile: each thread computes row tid ----
    {
        float th[8];
#pragma unroll
        for (int w = 0; w < 8; w++) th[w] = __ldg(theta + w);
        const float4* xr = reinterpret_cast<const float4*>(
            x + ((b * Ss + tid) * Ee + h * 8));
        float4 x0 = xr[0];
        float4 x1 = xr[1];
        float a[8] = {x0.x, x0.y, x0.z, x0.w, x1.x, x1.y, x1.z, x1.w};
        float c[8];
#pragma unroll
        for (int w = 0; w < 8; w++) c[w] = __cosf(a[w] + th[w]);
        float z[8];
        float pre = c[0];
#pragma unroll
        for (int w = 1; w < 8; w++) { pre *= c[w]; z[w] = pre; }
        float suf = 1.0f;
#pragma unroll
        for (int w = 7; w >= 1; w--) suf *= c[w];
        z[0] = suf;
#pragma unroll
        for (int d = 0; d < 8; d++) qsT[d * Ss + tid] = z[d];
    }
    __syncthreads();

    const int pr = tid & 127;
    const int g  = tid >> 7;
    const int sA = half * 256 + pr;
    const int sB = sA + 128;

    // queries, scaled by 1/sqrt(8)*log2(e), broadcast into packed lanes
    const float kscale = 0.35355339059327373f * 1.4426950408889634f;
    uint64_t mA[8], mB[8];
#pragma unroll
    for (int d = 0; d < 8; d++) {
        float ma = qsT[d * Ss + sA] * kscale;
        float mb = qsT[d * Ss + sB] * kscale;
        mA[d] = pack2(ma, ma);
        mB[d] = pack2(mb, mb);
    }

    uint64_t accA[8], accB[8];
#pragma unroll
    for (int d = 0; d < 8; d++) { accA[d] = 0; accB[d] = 0; }
    uint64_t lA = 0, lB = 0;

    const int t0 = g * 128;
#pragma unroll 1
    for (int t = t0; t < t0 + 128; t += 4) {
        // keys t..t+3 for all 8 dims: broadcast LDS.128, shared by both rows
        ulonglong2 kd[8];
#pragma unroll
        for (int d = 0; d < 8; d++)
            kd[d] = *reinterpret_cast<const ulonglong2*>(qsT + d * Ss + t);

        uint64_t xa, ya, xb, yb;     // 4 independent packed score chains
        MUL_X2(xa, mA[0], kd[0].x);
        MUL_X2(ya, mA[0], kd[0].y);
        MUL_X2(xb, mB[0], kd[0].x);
        MUL_X2(yb, mB[0], kd[0].y);
#pragma unroll
        for (int d = 1; d < 8; d++) {
            FMA_X2(xa, mA[d], kd[d].x, xa);
            FMA_X2(ya, mA[d], kd[d].y, ya);
            FMA_X2(xb, mB[d], kd[d].x, xb);
            FMA_X2(yb, mB[d], kd[d].y, yb);
        }
        float s0, s1, s2, s3, s4, s5, s6, s7;
        unpack2(xa, s0, s1); unpack2(ya, s2, s3);
        unpack2(xb, s4, s5); unpack2(yb, s6, s7);
        float p0, p1, p2, p3, p4, p5, p6, p7;
        asm("ex2.approx.f32 %0, %1;" : "=f"(p0) : "f"(s0));
        asm("ex2.approx.f32 %0, %1;" : "=f"(p1) : "f"(s1));
        asm("ex2.approx.f32 %0, %1;" : "=f"(p2) : "f"(s2));
        asm("ex2.approx.f32 %0, %1;" : "=f"(p3) : "f"(s3));
        asm("ex2.approx.f32 %0, %1;" : "=f"(p4) : "f"(s4));
        asm("ex2.approx.f32 %0, %1;" : "=f"(p5) : "f"(s5));
        asm("ex2.approx.f32 %0, %1;" : "=f"(p6) : "f"(s6));
        asm("ex2.approx.f32 %0, %1;" : "=f"(p7) : "f"(s7));
        uint64_t pA1 = pack2(p0, p1), pA2 = pack2(p2, p3);
        uint64_t pB1 = pack2(p4, p5), pB2 = pack2(p6, p7);
        ADD_X2(lA, lA, pA1); ADD_X2(lA, lA, pA2);
        ADD_X2(lB, lB, pB1); ADD_X2(lB, lB, pB2);
#pragma unroll
        for (int d = 0; d < 8; d++) {
            FMA_X2(accA[d], pA1, kd[d].x, accA[d]);
            FMA_X2(accA[d], pA2, kd[d].y, accA[d]);
            FMA_X2(accB[d], pB1, kd[d].x, accB[d]);
            FMA_X2(accB[d], pB2, kd[d].y, accB[d]);
        }
    }

    // ---- combine the four key groups: 3 sequential rounds through part ----
#pragma unroll 1
    for (int src = 1; src < 4; src++) {
        __syncthreads();
        if (g == src) {
            uint64_t* prow = part + pr * 18;
#pragma unroll
            for (int d = 0; d < 8; d++) { prow[d] = accA[d]; prow[8 + d] = accB[d]; }
            prow[16] = lA; prow[17] = lB;
        }
        __syncthreads();
        if (g == 0) {
            const uint64_t* prow = part + pr * 18;
#pragma unroll
            for (int d = 0; d < 8; d++) {
                ADD_X2(accA[d], accA[d], prow[d]);
                ADD_X2(accB[d], accB[d], prow[8 + d]);
            }
            ADD_X2(lA, lA, prow[16]);
            ADD_X2(lB, lB, prow[17]);
        }
    }

    if (g == 0) {
        float lo, hi;
        unpack2(lA, lo, hi);
        float invA = __frcp_rn(lo + hi);
        unpack2(lB, lo, hi);
        float invB = __frcp_rn(lo + hi);
        float rA[8], rB[8];
#pragma unroll
        for (int d = 0; d < 8; d++) {
            unpack2(accA[d], lo, hi); rA[d] = (lo + hi) * invA;
            unpack2(accB[d], lo, hi); rB[d] = (lo + hi) * invB;
        }
        float4* oA = reinterpret_cast<float4*>(
            g_ctx + ((b * Ss + sA) * Ee + h * 8));
        oA[0] = make_float4(rA[0], rA[1], rA[2], rA[3]);
        oA[1] = make_float4(rA[4], rA[5], rA[6], rA[7]);
        float4* oB = reinterpret_cast<float4*>(
            g_ctx + ((b * Ss + sB) * Ee + h * 8));
        oB[0] = make_float4(rB[0], rB[1], rB[2], rB[3]);
        oB[1] = make_float4(rB[4], rB[5], rB[6], rB[7]);
    }
}

// ---------------------------------------------------------------------------
// Kernel 2: out = ctx @ W_o^T + b_o.  ctx: [4096, 64], W_o: [64, 64].
// 32 rows/block (grid 128, single wave), 8 outputs/thread.
// ---------------------------------------------------------------------------
__global__ __launch_bounds__(256) void proj_kernel(
        const float* __restrict__ Wo,
        const float* __restrict__ bo,
        float* __restrict__ out) {
    __shared__ float Wt[64 * 65];             // Wt[e*65 + j] = Wo[j*64 + e]
    __shared__ float rows[PROJ_ROWS * 64];
    const int tid = threadIdx.x;              // 256

    // W fill: float4 loads, transposed scatter stores
    const float4* Wo4 = reinterpret_cast<const float4*>(Wo);
#pragma unroll
    for (int i = tid; i < 1024; i += 256) {
        float4 w = Wo4[i];
        int j = i >> 4, e0 = (i & 15) * 4;
        Wt[(e0 + 0) * 65 + j] = w.x;
        Wt[(e0 + 1) * 65 + j] = w.y;
        Wt[(e0 + 2) * 65 + j] = w.z;
        Wt[(e0 + 3) * 65 + j] = w.w;
    }
    const int row0 = blockIdx.x * PROJ_ROWS;
    const float4* c4 = reinterpret_cast<const float4*>(g_ctx + row0 * 64);
    float4* r4 = reinterpret_cast<float4*>(rows);
#pragma unroll
    for (int i = tid; i < PROJ_ROWS * 16; i += 256) r4[i] = c4[i];
    __syncthreads();

    const int j = tid & 63, rb = tid >> 6;    // rb in 0..3
    float bj = bo[j];
    float acc[8];
#pragma unroll
    for (int k = 0; k < 8; k++) acc[k] = bj;
#pragma unroll
    for (int e = 0; e < 64; e++) {
        float w = Wt[e * 65 + j];
#pragma unroll
        for (int k = 0; k < 8; k++)
            acc[k] = fmaf(rows[(rb + 4 * k) * 64 + e], w, acc[k]);
    }
#pragma unroll
    for (int k = 0; k < 8; k++)
        out[(row0 + rb + 4 * k) * 64 + j] = acc[k];
}

// ---------------------------------------------------------------------------
extern "C" void kernel_launch(void* const* d_in, const int* in_sizes, int n_in,
                              void* d_out, int out_size) {
    const float* x     = (const float*)d_in[0];
    const float* theta = (const float*)d_in[1];
    const float* Wo    = (const float*)d_in[2];
    const float* bo    = (const float*)d_in[3];
    float* out = (float*)d_out;
    (void)in_sizes; (void)n_in; (void)out_size;

    attn_fused_kernel<<<Bb * Hh * 2, 512>>>(x, theta);
    proj_kernel<<<(Bb * Ss) / PROJ_ROWS, 256>>>(Wo, bo, out);
}